// round 12
// baseline (speedup 1.0000x reference)
#include <cuda_runtime.h>

// GraphConvolution_LEGNN: out = 0.9 * rownorm1(A ⊙ same_class_mask) @ x + 0.1 * h0
// y one-hot -> mask[i][j] = (label[i]==label[j]); A ∈ {0,1}.
// R8-R10 lessons: scattered 4B gather caps at ~5.8TB/s with ~128B-line fills
//   (~373MB) under every policy/order/MLP variant -> ~64us main, hard floor.
// R11: dense SEQUENTIAL stream of A (400MB) at the streaming ceiling instead.
//   Fix R1's defects: same-class test via SHARED bitmap (no scattered global
//   label loads in the stream loop) and a one-branch any-nonzero test
//   (A >= 0 so sum of float4 != 0 <=> any element != 0).
//
// Inputs: d_in[0]=x [N,F] f32, d_in[1]=A [N,N] f32, d_in[2]=h0 [N,F] f32,
//         d_in[3]=y [N,C] f32.  Output: f32 [N,F].

#define N_NODES 10000
#define F_DIM   256
#define C_CLS   16
#define CAP     1024              // per-row neighbor capacity (expected ~6)
#define BM_WORDS ((N_NODES + 31) / 32)   // 313 words per class bitmap

__device__ int      g_labels[N_NODES];
__device__ unsigned g_bitmap[C_CLS][BM_WORDS];  // zero at load; self-reset each replay
__device__ int      g_done;                     // ticket; zero at load; self-reset

// Wide parallel prep: label from one-hot row (exact iota dot), set class bit.
__global__ __launch_bounds__(256)
void prep_kernel(const float* __restrict__ y) {
    int i = blockIdx.x * blockDim.x + threadIdx.x;
    if (i >= N_NODES) return;
    const float* yr = y + (size_t)i * C_CLS;
    float s = 0.0f;
#pragma unroll
    for (int k = 0; k < C_CLS; ++k) s = fmaf((float)k, yr[k], s);
    int lab = __float2int_rn(s);
    g_labels[i] = lab;
    atomicOr(&g_bitmap[lab][i >> 5], 1u << (i & 31));
}

__global__ __launch_bounds__(F_DIM)
void gcn_row_kernel(const float* __restrict__ x,
                    const float* __restrict__ A,
                    const float* __restrict__ h0,
                    float* __restrict__ out) {
    __shared__ unsigned s_bm[BM_WORDS];
    __shared__ int      s_idx[CAP];
    __shared__ float    s_val[CAP];
    __shared__ int      s_cnt;

    const int row = blockIdx.x;
    const int tid = threadIdx.x;

    if (tid == 0) s_cnt = 0;
    const int myc = g_labels[row];
    // Stage my class bitmap into shared (313 words).
    for (int w = tid; w < BM_WORDS; w += F_DIM) s_bm[w] = g_bitmap[myc][w];
    __syncthreads();

    // Stream the full A row sequentially (float4, evict-first). A >= 0, so the
    // horizontal sum is a one-branch exact any-nonzero test (96% skip rate).
    const float4* __restrict__ Arow4 =
        reinterpret_cast<const float4*>(A + (size_t)row * N_NODES);
    const int n4 = N_NODES / 4;  // 2500, exact

    for (int j4 = tid; j4 < n4; j4 += F_DIM) {
        float4 a = __ldcs(&Arow4[j4]);
        if ((a.x + a.y) + (a.z + a.w) != 0.0f) {
            int base = j4 << 2;
#pragma unroll
            for (int k = 0; k < 4; ++k) {
                float av = (k == 0) ? a.x : (k == 1) ? a.y : (k == 2) ? a.z : a.w;
                if (av != 0.0f) {
                    int col = base + k;
                    if (s_bm[col >> 5] & (1u << (col & 31))) {
                        int p = atomicAdd(&s_cnt, 1);
                        if (p < CAP) { s_idx[p] = col; s_val[p] = av; }
                    }
                }
            }
        }
    }
    __syncthreads();

    const int cnt = min(s_cnt, CAP);

    // Drain: thread tid owns feature column tid; x rows are L2 hits.
    float acc = 0.0f, sumw = 0.0f;
    int k = 0;
    for (; k + 4 <= cnt; k += 4) {
        int   c0 = s_idx[k],     c1 = s_idx[k + 1];
        int   c2 = s_idx[k + 2], c3 = s_idx[k + 3];
        float w0 = s_val[k],     w1 = s_val[k + 1];
        float w2 = s_val[k + 2], w3 = s_val[k + 3];
        float v0 = __ldg(&x[(size_t)c0 * F_DIM + tid]);
        float v1 = __ldg(&x[(size_t)c1 * F_DIM + tid]);
        float v2 = __ldg(&x[(size_t)c2 * F_DIM + tid]);
        float v3 = __ldg(&x[(size_t)c3 * F_DIM + tid]);
        acc  += w0 * v0 + w1 * v1 + w2 * v2 + w3 * v3;
        sumw += w0 + w1 + w2 + w3;
    }
    for (; k < cnt; ++k) {
        float w = s_val[k];
        acc  += w * __ldg(&x[(size_t)s_idx[k] * F_DIM + tid]);
        sumw += w;
    }

    float rs = fmaxf(sumw, 1e-12f);
    size_t o = (size_t)row * F_DIM + tid;
    float res = 0.9f * (acc / rs) + 0.1f * __ldcs(&h0[o]);
    __stcs(&out[o], res);

    // Self-reset for next replay: last block zeroes all bitmaps + ticket.
    // Every block's bitmap reads precede its ticket increment, so the reset
    // cannot be observed early.
    __syncthreads();
    if (tid == 0) { __threadfence(); }
    __syncthreads();
    if (tid == 0) s_cnt = atomicAdd(&g_done, 1);  // reuse s_cnt as ticket slot
    __syncthreads();
    if (s_cnt == gridDim.x - 1) {
        unsigned* bm = &g_bitmap[0][0];
        for (int w = tid; w < C_CLS * BM_WORDS; w += F_DIM) bm[w] = 0;
        if (tid == 0) g_done = 0;
    }
}

extern "C" void kernel_launch(void* const* d_in, const int* in_sizes, int n_in,
                              void* d_out, int out_size) {
    const float* x  = (const float*)d_in[0];
    const float* A  = (const float*)d_in[1];
    const float* h0 = (const float*)d_in[2];
    const float* y  = (const float*)d_in[3];
    float* out = (float*)d_out;

    prep_kernel<<<(N_NODES + 255) / 256, 256>>>(y);
    gcn_row_kernel<<<N_NODES, F_DIM>>>(x, A, h0, out);
}

// round 13
// speedup vs baseline: 1.4202x; 1.4202x over previous
#include <cuda_runtime.h>

// GraphConvolution_LEGNN: out = 0.9 * rownorm1(A ⊙ same_class_mask) @ x + 0.1 * h0
// y one-hot -> mask[i][j] = (label[i]==label[j]); A ∈ {0,1}.
// Converged design: per-class column lists; each row scatters ~625 4B A-loads.
// Evidence ledger:
//   - scatter BW ceiling 5.8TB/s (order/policy/L1-bypass/MLP/scheduling all
//     neutral) = HBM random-128B-fill efficiency; bytes ~381MB are all needed.
//   - streaming is ISSUE-bound: ~4.5 instr/16B -> <=4 instr/cyc/SM caps at
//     ~4TB/s (matches R1 4.49, R11 4.24). Can never beat scatter. Closed.
// R12: R10 winner + micro-opts: h0 prefetch overlapped with A gather; counter
//   reset moved before drain (overlaps instead of trailing).
//
// Inputs: d_in[0]=x [N,F] f32, d_in[1]=A [N,N] f32, d_in[2]=h0 [N,F] f32,
//         d_in[3]=y [N,C] f32.  Output: f32 [N,F].

#define N_NODES 10000
#define F_DIM   256
#define C_CLS   16
#define CAP     1024   // per-row neighbor capacity (expected ~6, worst ~40)

__device__ int g_labels[N_NODES];
__device__ int g_ccnt[C_CLS];          // zero at module load; self-reset each launch
__device__ int g_done;                 // ticket; zero at load; self-reset
__device__ int g_cols[C_CLS * N_NODES];

// Single-use global load: no L1 allocation, read-only path.
__device__ __forceinline__ float ldg_noL1(const float* p) {
    float v;
    asm volatile("ld.global.nc.L1::no_allocate.f32 %0, [%1];"
                 : "=f"(v) : "l"(p));
    return v;
}

// Wide parallel prep: label from one-hot row (exact iota dot), write labels,
// atomic scatter into class list (order irrelevant).
__global__ __launch_bounds__(256)
void prep_kernel(const float* __restrict__ y) {
    int i = blockIdx.x * blockDim.x + threadIdx.x;
    if (i >= N_NODES) return;
    const float* yr = y + (size_t)i * C_CLS;
    float s = 0.0f;
#pragma unroll
    for (int k = 0; k < C_CLS; ++k) s = fmaf((float)k, yr[k], s);
    int lab = __float2int_rn(s);
    g_labels[i] = lab;
    int p = atomicAdd(&g_ccnt[lab], 1);
    g_cols[lab * N_NODES + p] = i;
}

__global__ __launch_bounds__(F_DIM)
void gcn_row_kernel(const float* __restrict__ x,
                    const float* __restrict__ A,
                    const float* __restrict__ h0,
                    float* __restrict__ out) {
    __shared__ int   s_idx[CAP];
    __shared__ float s_val[CAP];
    __shared__ int   s_cnt;
    __shared__ int   s_ticket;

    const int row = blockIdx.x;
    const int tid = threadIdx.x;

    if (tid == 0) s_cnt = 0;
    __syncthreads();

    const int myc  = g_labels[row];
    const int ccnt = g_ccnt[myc];
    const int* __restrict__ clist = g_cols + myc * N_NODES;
    const float* __restrict__ Arow = A + (size_t)row * N_NODES;

    // Prefetch h0 early: its DRAM latency hides under the A gather.
    const size_t o = (size_t)row * F_DIM + tid;
    const float h0v = __ldcs(&h0[o]);

    // Gather same-class columns; A loads bypass L1 allocation (single-use).
    {
        const int k0 = tid, k1 = tid + F_DIM, k2 = tid + 2 * F_DIM;
        const bool p0 = k0 < ccnt, p1 = k1 < ccnt, p2 = k2 < ccnt;
        int c0 = 0, c1 = 0, c2 = 0;
        if (p0) c0 = __ldg(&clist[k0]);
        if (p1) c1 = __ldg(&clist[k1]);
        if (p2) c2 = __ldg(&clist[k2]);
        float a0 = 0.0f, a1 = 0.0f, a2 = 0.0f;
        if (p0) a0 = ldg_noL1(&Arow[c0]);
        if (p1) a1 = ldg_noL1(&Arow[c1]);
        if (p2) a2 = ldg_noL1(&Arow[c2]);
        if (a0 != 0.0f) { int p = atomicAdd(&s_cnt, 1); if (p < CAP) { s_idx[p] = c0; s_val[p] = a0; } }
        if (a1 != 0.0f) { int p = atomicAdd(&s_cnt, 1); if (p < CAP) { s_idx[p] = c1; s_val[p] = a1; } }
        if (a2 != 0.0f) { int p = atomicAdd(&s_cnt, 1); if (p < CAP) { s_idx[p] = c2; s_val[p] = a2; } }
        // Generality tail (not taken for this distribution: ccnt ~ 625 +/- 24).
        for (int k = 3 * F_DIM + tid; k < ccnt; k += F_DIM) {
            int col  = __ldg(&clist[k]);
            float av = ldg_noL1(&Arow[col]);
            if (av != 0.0f) { int p = atomicAdd(&s_cnt, 1); if (p < CAP) { s_idx[p] = col; s_val[p] = av; } }
        }
    }
    __syncthreads();

    // Early ticket: all g_ccnt reads for this CTA are done (CTA start), so the
    // last CTA may reset counters NOW; the zeroing overlaps the drain below.
    if (tid == 0) {
        __threadfence();
        s_ticket = atomicAdd(&g_done, 1);
    }

    const int cnt = min(s_cnt, CAP);

    // Drain: thread tid owns feature column tid; x rows are L2 hits.
    float acc = 0.0f, sumw = 0.0f;
    int k = 0;
    for (; k + 4 <= cnt; k += 4) {
        int   c0 = s_idx[k],     c1 = s_idx[k + 1];
        int   c2 = s_idx[k + 2], c3 = s_idx[k + 3];
        float w0 = s_val[k],     w1 = s_val[k + 1];
        float w2 = s_val[k + 2], w3 = s_val[k + 3];
        float v0 = __ldg(&x[(size_t)c0 * F_DIM + tid]);
        float v1 = __ldg(&x[(size_t)c1 * F_DIM + tid]);
        float v2 = __ldg(&x[(size_t)c2 * F_DIM + tid]);
        float v3 = __ldg(&x[(size_t)c3 * F_DIM + tid]);
        acc  += w0 * v0 + w1 * v1 + w2 * v2 + w3 * v3;
        sumw += w0 + w1 + w2 + w3;
    }
    for (; k < cnt; ++k) {
        float w = s_val[k];
        acc  += w * __ldg(&x[(size_t)s_idx[k] * F_DIM + tid]);
        sumw += w;
    }

    float rs = fmaxf(sumw, 1e-12f);
    float res = 0.9f * (acc / rs) + 0.1f * h0v;
    __stcs(&out[o], res);   // write-once stream

    // Last CTA resets counters for the next graph replay.
    __syncthreads();
    if (tid == 0 && s_ticket == gridDim.x - 1) {
#pragma unroll
        for (int c = 0; c < C_CLS; ++c) g_ccnt[c] = 0;
        g_done = 0;
    }
}

extern "C" void kernel_launch(void* const* d_in, const int* in_sizes, int n_in,
                              void* d_out, int out_size) {
    const float* x  = (const float*)d_in[0];
    const float* A  = (const float*)d_in[1];
    const float* h0 = (const float*)d_in[2];
    const float* y  = (const float*)d_in[3];
    float* out = (float*)d_out;

    prep_kernel<<<(N_NODES + 255) / 256, 256>>>(y);
    gcn_row_kernel<<<N_NODES, F_DIM>>>(x, A, h0, out);
}

// round 14
// speedup vs baseline: 1.5622x; 1.1000x over previous
#include <cuda_runtime.h>

// GraphConvolution_LEGNN: out = 0.9 * rownorm1(A ⊙ same_class_mask) @ x + 0.1 * h0
// y one-hot -> mask[i][j] = (label[i]==label[j]); A ∈ {0,1}.
// Converged design: per-class column lists; each row scatters ~625 4B A-loads.
// Evidence ledger:
//   - scatter BW ceiling ~5.8TB/s; bytes ~381MB all necessary. Order/policy/
//     L1-bypass/MLP/scheduling all neutral.
//   - streaming is issue-bound (~4TB/s). Closed.
//   - R12 lesson: do NOT put loads/fences inside or adjacent to the gather
//     window (h0-prefetch + mid-kernel fence cost 6us). Epilogue work stays
//     in the epilogue.
// R13: exact R10 structure; sole change = h0 load issued at top of drain so it
//   overlaps the x-FFMA loop instead of trailing it.
//
// Inputs: d_in[0]=x [N,F] f32, d_in[1]=A [N,N] f32, d_in[2]=h0 [N,F] f32,
//         d_in[3]=y [N,C] f32.  Output: f32 [N,F].

#define N_NODES 10000
#define F_DIM   256
#define C_CLS   16
#define CAP     1024   // per-row neighbor capacity (expected ~6, worst ~40)

__device__ int g_labels[N_NODES];
__device__ int g_ccnt[C_CLS];          // zero at module load; self-reset each launch
__device__ int g_done;                 // ticket; zero at load; self-reset
__device__ int g_cols[C_CLS * N_NODES];

// Single-use global load: no L1 allocation, read-only path.
__device__ __forceinline__ float ldg_noL1(const float* p) {
    float v;
    asm volatile("ld.global.nc.L1::no_allocate.f32 %0, [%1];"
                 : "=f"(v) : "l"(p));
    return v;
}

// Wide parallel prep: label from one-hot row (exact iota dot), write labels,
// atomic scatter into class list (order irrelevant).
__global__ __launch_bounds__(256)
void prep_kernel(const float* __restrict__ y) {
    int i = blockIdx.x * blockDim.x + threadIdx.x;
    if (i >= N_NODES) return;
    const float* yr = y + (size_t)i * C_CLS;
    float s = 0.0f;
#pragma unroll
    for (int k = 0; k < C_CLS; ++k) s = fmaf((float)k, yr[k], s);
    int lab = __float2int_rn(s);
    g_labels[i] = lab;
    int p = atomicAdd(&g_ccnt[lab], 1);
    g_cols[lab * N_NODES + p] = i;
}

__global__ __launch_bounds__(F_DIM)
void gcn_row_kernel(const float* __restrict__ x,
                    const float* __restrict__ A,
                    const float* __restrict__ h0,
                    float* __restrict__ out) {
    __shared__ int   s_idx[CAP];
    __shared__ float s_val[CAP];
    __shared__ int   s_cnt;

    const int row = blockIdx.x;
    const int tid = threadIdx.x;

    if (tid == 0) s_cnt = 0;
    __syncthreads();

    const int myc  = g_labels[row];
    const int ccnt = g_ccnt[myc];
    const int* __restrict__ clist = g_cols + myc * N_NODES;
    const float* __restrict__ Arow = A + (size_t)row * N_NODES;

    // Gather same-class columns; A loads bypass L1 allocation (single-use).
    // NOTHING else shares this phase's memory-queue window (R12 lesson).
    {
        const int k0 = tid, k1 = tid + F_DIM, k2 = tid + 2 * F_DIM;
        const bool p0 = k0 < ccnt, p1 = k1 < ccnt, p2 = k2 < ccnt;
        int c0 = 0, c1 = 0, c2 = 0;
        if (p0) c0 = __ldg(&clist[k0]);
        if (p1) c1 = __ldg(&clist[k1]);
        if (p2) c2 = __ldg(&clist[k2]);
        float a0 = 0.0f, a1 = 0.0f, a2 = 0.0f;
        if (p0) a0 = ldg_noL1(&Arow[c0]);
        if (p1) a1 = ldg_noL1(&Arow[c1]);
        if (p2) a2 = ldg_noL1(&Arow[c2]);
        if (a0 != 0.0f) { int p = atomicAdd(&s_cnt, 1); if (p < CAP) { s_idx[p] = c0; s_val[p] = a0; } }
        if (a1 != 0.0f) { int p = atomicAdd(&s_cnt, 1); if (p < CAP) { s_idx[p] = c1; s_val[p] = a1; } }
        if (a2 != 0.0f) { int p = atomicAdd(&s_cnt, 1); if (p < CAP) { s_idx[p] = c2; s_val[p] = a2; } }
        // Generality tail (not taken for this distribution: ccnt ~ 625 +/- 24).
        for (int k = 3 * F_DIM + tid; k < ccnt; k += F_DIM) {
            int col  = __ldg(&clist[k]);
            float av = ldg_noL1(&Arow[col]);
            if (av != 0.0f) { int p = atomicAdd(&s_cnt, 1); if (p < CAP) { s_idx[p] = col; s_val[p] = av; } }
        }
    }
    __syncthreads();

    const int cnt = min(s_cnt, CAP);

    // Drain: issue h0 first so its latency hides under the x-FFMA loop.
    const size_t o = (size_t)row * F_DIM + tid;
    const float h0v = __ldcs(&h0[o]);

    float acc = 0.0f, sumw = 0.0f;
    int k = 0;
    for (; k + 4 <= cnt; k += 4) {
        int   c0 = s_idx[k],     c1 = s_idx[k + 1];
        int   c2 = s_idx[k + 2], c3 = s_idx[k + 3];
        float w0 = s_val[k],     w1 = s_val[k + 1];
        float w2 = s_val[k + 2], w3 = s_val[k + 3];
        float v0 = __ldg(&x[(size_t)c0 * F_DIM + tid]);
        float v1 = __ldg(&x[(size_t)c1 * F_DIM + tid]);
        float v2 = __ldg(&x[(size_t)c2 * F_DIM + tid]);
        float v3 = __ldg(&x[(size_t)c3 * F_DIM + tid]);
        acc  += w0 * v0 + w1 * v1 + w2 * v2 + w3 * v3;
        sumw += w0 + w1 + w2 + w3;
    }
    for (; k < cnt; ++k) {
        float w = s_val[k];
        acc  += w * __ldg(&x[(size_t)s_idx[k] * F_DIM + tid]);
        sumw += w;
    }

    float rs = fmaxf(sumw, 1e-12f);
    float res = 0.9f * (acc / rs) + 0.1f * h0v;
    __stcs(&out[o], res);   // write-once stream

    // Self-reset for next graph replay: last block zeroes the counters. This
    // block's g_ccnt reads precede the ticket (sync + program order).
    __syncthreads();
    if (tid == 0) {
        __threadfence();
        int t = atomicAdd(&g_done, 1);
        if (t == gridDim.x - 1) {
#pragma unroll
            for (int c = 0; c < C_CLS; ++c) g_ccnt[c] = 0;
            g_done = 0;
        }
    }
}

extern "C" void kernel_launch(void* const* d_in, const int* in_sizes, int n_in,
                              void* d_out, int out_size) {
    const float* x  = (const float*)d_in[0];
    const float* A  = (const float*)d_in[1];
    const float* h0 = (const float*)d_in[2];
    const float* y  = (const float*)d_in[3];
    float* out = (float*)d_out;

    prep_kernel<<<(N_NODES + 255) / 256, 256>>>(y);
    gcn_row_kernel<<<N_NODES, F_DIM>>>(x, A, h0, out);
}